// round 9
// baseline (speedup 1.0000x reference)
#include <cuda_runtime.h>
#include <cstdint>

// Problem constants (fixed by the reference).
#define BB   4
#define DD   128
#define HH   128
#define WW   128
#define NMAX 500000
#define CIN  32
#define COUT 32
#define KVOL 125
#define GRID_SZ (BB * DD * HH * WW)   // 8,388,608
#define NBUCK (GRID_SZ / 512)         // 16384 buckets of 512 voxels (4 x-rows)
#define EPSV 1e-4f
#define FULLMASK 0xffffffffu
#define SITES_PER_BLOCK 2048          // 256 threads x 8 iterations

// -------- device scratch (allocation-free: static __device__ globals) --------
__device__ int   g_grid[GRID_SZ];          // flat voxel -> RANK (-1 inactive)
__device__ int   g_flat[NMAX];             // site (original order) -> flat idx
__device__ int   g_sflat[NMAX];            // rank -> flat idx (bucket-sorted)
__device__ int   g_orig[NMAX];             // rank -> original site row
__device__ int   g_hist[NBUCK];            // bucket histogram -> bases
__device__ __align__(16) float g_feat[(size_t)NMAX * CIN]; // rank-ordered feats
__device__ __align__(16) float g_acc[(size_t)NMAX * CIN];  // rank-ordered output
__device__ float g_stats[2 * CIN];

// f32x2 packed FMA — PTX only.
#define FFMA2(acc, f2, w2) \
    asm("fma.rn.f32x2 %0, %1, %2, %3;" : "=l"(acc) : "l"(f2), "l"(w2), "l"(acc))

// -------- kernel 1: reset grid to -1, zero acc/hist/stats -------------------
__global__ void k_reset(int accElems4) {
    int i = blockIdx.x * blockDim.x + threadIdx.x;
    int stride = gridDim.x * blockDim.x;
    int4 m1 = make_int4(-1, -1, -1, -1);
    for (int e = i; e < GRID_SZ / 4; e += stride)
        reinterpret_cast<int4*>(g_grid)[e] = m1;
    float4 z4 = make_float4(0.f, 0.f, 0.f, 0.f);
    for (int e = i; e < accElems4; e += stride)
        reinterpret_cast<float4*>(g_acc)[e] = z4;
    for (int e = i; e < NBUCK; e += stride) g_hist[e] = 0;
    if (blockIdx.x == 0 && threadIdx.x < 2 * CIN) g_stats[threadIdx.x] = 0.f;
}

// -------- kernel 2: scatter sites + bucket histogram + BN stats -------------
__global__ void k_scatter_stats(const float* __restrict__ x,
                                const int* __restrict__ coords, int Nv) {
    int tid = threadIdx.x;
    int i0 = blockIdx.x * blockDim.x + tid;
    int stride = gridDim.x * blockDim.x;   // multiple of 32

    for (int i = i0; i < Nv; i += stride) {
        int4 c = reinterpret_cast<const int4*>(coords)[i];  // b, z, y, x
        int fl = (((c.x * DD + c.y) * HH + c.z) * WW) + c.w;
        g_grid[fl] = i;       // temp: site id (rewritten to rank later)
        g_flat[i] = fl;
        atomicAdd(&g_hist[fl >> 9], 1);
    }

    // per-channel sum / sumsq (lane channel fixed since stride % 32 == 0)
    __shared__ float ss[8][33];
    __shared__ float ss2[8][33];
    int c = tid & 31;
    int wid = tid >> 5;
    float s = 0.f, s2 = 0.f;
    int total = Nv * CIN;
    for (int e = i0; e < total; e += stride) {
        float v = x[e];
        s += v;
        s2 += v * v;
    }
    ss[wid][c] = s;
    ss2[wid][c] = s2;
    __syncthreads();
    if (tid < 32) {
        float a = 0.f, b = 0.f;
#pragma unroll
        for (int k = 0; k < 8; k++) { a += ss[k][tid]; b += ss2[k][tid]; }
        atomicAdd(&g_stats[tid], a);
        atomicAdd(&g_stats[32 + tid], b);
    }
}

// -------- kernel 3: exclusive scan of the bucket histogram ------------------
__global__ void __launch_bounds__(1024) k_scan() {
    __shared__ int part[1024];
    int tid = threadIdx.x;
    int local[16];
    int s = 0;
#pragma unroll
    for (int k = 0; k < 16; k++) { local[k] = s; s += g_hist[tid * 16 + k]; }
    part[tid] = s;
    __syncthreads();
    // Hillis-Steele inclusive scan over 1024 partials
    for (int d = 1; d < 1024; d <<= 1) {
        int v = (tid >= d) ? part[tid - d] : 0;
        __syncthreads();
        part[tid] += v;
        __syncthreads();
    }
    int base = (tid == 0) ? 0 : part[tid - 1];
#pragma unroll
    for (int k = 0; k < 16; k++) g_hist[tid * 16 + k] = base + local[k];
}

// -------- kernel 4: assign ranks, rewrite grid to rank ids ------------------
__global__ void k_rank(int Nv) {
    int i = blockIdx.x * blockDim.x + threadIdx.x;
    if (i < Nv) {
        int fl = g_flat[i];
        int r = atomicAdd(&g_hist[fl >> 9], 1);
        g_sflat[r] = fl;
        g_orig[r] = i;
        g_grid[fl] = r;
    }
}

// -------- kernel 5: rank-ordered y = relu(x*scale + bias) -------------------
__global__ void k_norm(const float* __restrict__ x,
                       const float* __restrict__ gamma,
                       const float* __restrict__ beta, int Nv) {
    __shared__ float sc[32], bi[32];
    if (threadIdx.x < 32) {
        int c = threadIdx.x;
        float invN = 1.0f / (float)Nv;
        float mean = g_stats[c] * invN;
        float var = g_stats[32 + c] * invN - mean * mean;
        float s = gamma[c] * rsqrtf(var + EPSV);
        sc[c] = s;
        bi[c] = beta[c] - mean * s;
    }
    __syncthreads();
    int e = blockIdx.x * blockDim.x + threadIdx.x;  // float4 units, rank order
    int total = Nv * (CIN / 4);
    if (e < total) {
        int r = e >> 3, q = e & 7;
        int row = g_orig[r];
        float4 v = reinterpret_cast<const float4*>(x)[row * 8 + q];
        int c0 = q * 4;
        float4 o;
        o.x = fmaxf(fmaf(v.x, sc[c0 + 0], bi[c0 + 0]), 0.f);
        o.y = fmaxf(fmaf(v.y, sc[c0 + 1], bi[c0 + 1]), 0.f);
        o.z = fmaxf(fmaf(v.z, sc[c0 + 2], bi[c0 + 2]), 0.f);
        o.w = fmaxf(fmaf(v.w, sc[c0 + 3], bi[c0 + 3]), 0.f);
        reinterpret_cast<float4*>(g_feat)[e] = o;
    }
}

// -------- kernel 6: sparse conv over ranks, one offset per blockIdx.y -------
// Identical compute structure to the proven R7 kernel, but all indices are
// bucket-sorted ranks: warp's sites are spatially contiguous -> coherent grid
// lookups, L1/L2-resident neighbor feature rows, contiguous vector REDs.
__global__ void __launch_bounds__(256) k_conv(const float* __restrict__ weight,
                                              int Nv) {
    const int o = blockIdx.y;
    const int dz = o / 25 - 2;
    const int dy = (o / 5) % 5 - 2;
    const int dx = o % 5 - 2;
    const int lane = threadIdx.x & 31;
    const int wid = threadIdx.x >> 5;

    __shared__ __align__(16) float tile[2][8][4][32];

    // Packed weight column: w2[t] = (W[2t][lane], W[2t+1][lane])
    unsigned long long w2[16];
    {
        const float* wp = weight + o * (CIN * COUT) + lane;
#pragma unroll
        for (int t = 0; t < 16; t++) {
            float a = __ldg(wp + (2 * t) * COUT);
            float b = __ldg(wp + (2 * t + 1) * COUT);
            asm("mov.b64 %0, {%1, %2};" : "=l"(w2[t]) : "f"(a), "f"(b));
        }
    }

    const int p  = lane >> 3;        // which of the 4 batched pairs this lane stores
    const int c4 = (lane & 7) * 4;   // cout base for the vector RED
    int buf = 0;

    const int blockBase = blockIdx.x * SITES_PER_BLOCK;
#pragma unroll 1
    for (int it = 0; it < SITES_PER_BLOCK / 256; it++) {
        const int base = blockBase + it * 256 + (threadIdx.x & ~31);
        const int site = base + lane;            // rank id
        int nidx = -1;
        if (site < Nv) {
            int fl = __ldg(&g_sflat[site]);
            int z = (fl >> 14) & 127, y = (fl >> 7) & 127, x = fl & 127;
            if (((unsigned)(z + dz) < 128u) & ((unsigned)(y + dy) < 128u) &
                ((unsigned)(x + dx) < 128u)) {
                nidx = g_grid[fl + dz * (HH * WW) + dy * WW + dx];  // rank id
            }
        }
        unsigned mask = __ballot_sync(FULLMASK, nidx >= 0);
        while (mask) {
            int js0 = 0, js1 = 0, js2 = 0, js3 = 0, cnt = 0;
            if (mask) { js0 = __ffs(mask) - 1; mask &= mask - 1; cnt = 1; }
            if (mask) { js1 = __ffs(mask) - 1; mask &= mask - 1; cnt = 2; }
            if (mask) { js2 = __ffs(mask) - 1; mask &= mask - 1; cnt = 3; }
            if (mask) { js3 = __ffs(mask) - 1; mask &= mask - 1; cnt = 4; }

            int n0 = __shfl_sync(FULLMASK, nidx, js0);
            int n1 = __shfl_sync(FULLMASK, nidx, js1);
            int n2 = __shfl_sync(FULLMASK, nidx, js2);
            int n3 = __shfl_sync(FULLMASK, nidx, js3);
            if (cnt < 2) n1 = n0;
            if (cnt < 3) n2 = n0;
            if (cnt < 4) n3 = n0;

            const ulonglong2* f0 = reinterpret_cast<const ulonglong2*>(g_feat + (size_t)n0 * CIN);
            const ulonglong2* f1 = reinterpret_cast<const ulonglong2*>(g_feat + (size_t)n1 * CIN);
            const ulonglong2* f2 = reinterpret_cast<const ulonglong2*>(g_feat + (size_t)n2 * CIN);
            const ulonglong2* f3 = reinterpret_cast<const ulonglong2*>(g_feat + (size_t)n3 * CIN);

            unsigned long long a0 = 0ull, a1 = 0ull, a2 = 0ull, a3 = 0ull;
#pragma unroll
            for (int t = 0; t < 8; t++) {
                ulonglong2 q0 = f0[t], q1 = f1[t], q2 = f2[t], q3 = f3[t];
                FFMA2(a0, q0.x, w2[2 * t]); FFMA2(a0, q0.y, w2[2 * t + 1]);
                FFMA2(a1, q1.x, w2[2 * t]); FFMA2(a1, q1.y, w2[2 * t + 1]);
                FFMA2(a2, q2.x, w2[2 * t]); FFMA2(a2, q2.y, w2[2 * t + 1]);
                FFMA2(a3, q3.x, w2[2 * t]); FFMA2(a3, q3.y, w2[2 * t + 1]);
            }
            float r0, r1, r2, r3;
            {
                float lo, hi;
                asm("mov.b64 {%0, %1}, %2;" : "=f"(lo), "=f"(hi) : "l"(a0)); r0 = lo + hi;
                asm("mov.b64 {%0, %1}, %2;" : "=f"(lo), "=f"(hi) : "l"(a1)); r1 = lo + hi;
                asm("mov.b64 {%0, %1}, %2;" : "=f"(lo), "=f"(hi) : "l"(a2)); r2 = lo + hi;
                asm("mov.b64 {%0, %1}, %2;" : "=f"(lo), "=f"(hi) : "l"(a3)); r3 = lo + hi;
            }
            if (cnt < 2) r1 = 0.f;
            if (cnt < 3) r2 = 0.f;
            if (cnt < 4) r3 = 0.f;

            // Transpose through smem: [pair][cout] tile, conflict-free.
            tile[buf][wid][0][lane] = r0;
            tile[buf][wid][1][lane] = r1;
            tile[buf][wid][2][lane] = r2;
            tile[buf][wid][3][lane] = r3;
            __syncwarp(FULLMASK);
            float4 v = *reinterpret_cast<const float4*>(&tile[buf][wid][p][c4]);
            if (p < cnt) {
                int jp = (p == 0) ? js0 : (p == 1) ? js1 : (p == 2) ? js2 : js3;
                float* dst = g_acc + (size_t)(base + jp) * COUT + c4;
                asm volatile("red.global.add.v4.f32 [%0], {%1, %2, %3, %4};"
                             :: "l"(dst), "f"(v.x), "f"(v.y), "f"(v.z), "f"(v.w)
                             : "memory");
            }
            buf ^= 1;   // double buffer: next STS goes to the other tile
        }
    }
}

// -------- kernel 7: permute accumulator back to original row order ----------
__global__ void k_permute(float* __restrict__ out, int Nv) {
    int e = blockIdx.x * blockDim.x + threadIdx.x;  // float4 units
    int total = Nv * (CIN / 4);
    if (e < total) {
        int r = e >> 3, q = e & 7;
        float4 v = reinterpret_cast<const float4*>(g_acc)[e];
        reinterpret_cast<float4*>(out)[g_orig[r] * 8 + q] = v;
    }
}

// -------- launch ------------------------------------------------------------
extern "C" void kernel_launch(void* const* d_in, const int* in_sizes, int n_in,
                              void* d_out, int out_size) {
    const float* feats  = (const float*)d_in[0];   // [N, 32]
    const int*   coords = (const int*)d_in[1];     // [N, 4]
    const float* gamma  = (const float*)d_in[2];   // [32]
    const float* beta   = (const float*)d_in[3];   // [32]
    const float* weight = (const float*)d_in[4];   // [125, 32, 32]
    float* out = (float*)d_out;                    // [N, 32]

    int Nv = in_sizes[0] / CIN;
    if (Nv > NMAX) Nv = NMAX;

    k_reset<<<4096, 256>>>(Nv * (CIN / 4));
    k_scatter_stats<<<1024, 256>>>(feats, coords, Nv);
    k_scan<<<1, 1024>>>();
    k_rank<<<(Nv + 255) / 256, 256>>>(Nv);
    k_norm<<<(Nv * (CIN / 4) + 255) / 256, 256>>>(feats, gamma, beta, Nv);

    dim3 gc((Nv + SITES_PER_BLOCK - 1) / SITES_PER_BLOCK, KVOL);
    k_conv<<<gc, 256>>>(weight, Nv);

    k_permute<<<(Nv * (CIN / 4) + 255) / 256, 256>>>(out, Nv);
}